// round 1
// baseline (speedup 1.0000x reference)
#include <cuda_runtime.h>
#include <cstdint>

// Problem shapes (fixed by setup_inputs)
#define NB    4
#define NH    12
#define BHN   48          // NB*NH
#define SEQ   1024
#define HD    64
#define TQ    128         // queries per CTA
#define TK    128         // keys per tile
#define NQT   (SEQ / TQ)  // 8 q-tiles
#define NTHREADS 128
#define LAM   0.01f
#define EPSV  1e-6f
#define CLV   20.0f
#define SCALE 0.125f      // 1/sqrt(64)

typedef unsigned long long u64;

// ---- packed fp32x2 helpers (Blackwell f32x2 pipe: 2 FMA per issue) ----
__device__ __forceinline__ u64 pk2(float lo, float hi) {
    u64 r; asm("mov.b64 %0, {%1,%2};" : "=l"(r) : "f"(lo), "f"(hi)); return r;
}
__device__ __forceinline__ void unpk2(u64 v, float& lo, float& hi) {
    asm("mov.b64 {%0,%1}, %2;" : "=f"(lo), "=f"(hi) : "l"(v));
}
__device__ __forceinline__ void fma2(u64& d, u64 a, u64 b) {
    asm("fma.rn.f32x2 %0, %1, %2, %0;" : "+l"(d) : "l"(a), "l"(b));
}
__device__ __forceinline__ u64 add2(u64 a, u64 b) {
    u64 r; asm("add.rn.f32x2 %0, %1, %2;" : "=l"(r) : "l"(a), "l"(b)); return r;
}
__device__ __forceinline__ u64 mul2(u64 a, u64 b) {
    u64 r; asm("mul.rn.f32x2 %0, %1, %2;" : "=l"(r) : "l"(a), "l"(b)); return r;
}

struct TrueT  { static constexpr bool value = true;  };
struct FalseT { static constexpr bool value = false; };

// Layout per CTA:
//   128 threads. Lane pair (2p, 2p+1) owns queries qA=q0+p and qB=q0+64+p.
//   Even lane of a pair holds dims [0,32), odd lane holds dims [32,64).
//   Dot products complete via one shfl_xor(.,1). The k-scan recurrence is
//   computed redundantly (identically) in both half-lanes.
__global__ void __launch_bounds__(NTHREADS, 2)
rse_attn(const float* __restrict__ gq, const float* __restrict__ gk,
         const float* __restrict__ gv, const float* __restrict__ gcos,
         const float* __restrict__ gsin, float* __restrict__ gout)
{
    extern __shared__ float smem[];
    float* shk = smem;            // TK x 64 (RoPE'd K)
    float* shv = smem + TK * HD;  // TK x 64 (V)

    const int tid  = threadIdx.x;
    const int idx  = blockIdx.x;
    const int qt   = (NQT - 1) - (idx / BHN);  // heavy q-tiles launch first
    const int bh   = idx % BHN;
    const int q0   = qt * TQ;
    const int half = tid & 1;
    const int p    = tid >> 1;                 // 0..63
    const int qA   = q0 + p;
    const int qB   = q0 + 64 + p;
    const float fqA = (float)qA;
    const float fqB = (float)qB;
    const size_t base = (size_t)bh * SEQ * HD;

    // ---- load + RoPE the two query rows (32 dims each = 16 f32x2) ----
    u64 q2A[16], q2B[16];
    {
        const float* ra = gq + base + (size_t)qA * HD + half * 32;
        const float* rb = gq + base + (size_t)qB * HD + half * 32;
        const float* ca = gcos + qA * 32 + half * 16;
        const float* sa = gsin + qA * 32 + half * 16;
        const float* cb = gcos + qB * 32 + half * 16;
        const float* sb = gsin + qB * 32 + half * 16;
        #pragma unroll
        for (int j = 0; j < 8; j++) {
            float4 x  = *(const float4*)(ra + 4 * j);
            float2 c  = *(const float2*)(ca + 2 * j);
            float2 s  = *(const float2*)(sa + 2 * j);
            q2A[2*j]   = pk2(x.x*c.x - x.y*s.x, x.y*c.x + x.x*s.x);
            q2A[2*j+1] = pk2(x.z*c.y - x.w*s.y, x.w*c.y + x.z*s.y);
            float4 y  = *(const float4*)(rb + 4 * j);
            float2 c2 = *(const float2*)(cb + 2 * j);
            float2 s2 = *(const float2*)(sb + 2 * j);
            q2B[2*j]   = pk2(y.x*c2.x - y.y*s2.x, y.y*c2.x + y.x*s2.x);
            q2B[2*j+1] = pk2(y.z*c2.y - y.w*s2.y, y.w*c2.y + y.z*s2.y);
        }
    }

    u64 accA[16], accB[16];
    #pragma unroll
    for (int i = 0; i < 16; i++) { accA[i] = 0ull; accB[i] = 0ull; }
    float remA = 1.f, remB = 1.f, wsA = 0.f, wsB = 0.f;

    // One key step. DOA selects (at compile time) whether query A participates.
    auto step = [&](int kk, int k0, auto doa, bool vA, bool vB) {
        constexpr bool DOA = decltype(doa)::value;
        const ulonglong2* kr = (const ulonglong2*)(shk + kk * HD + half * 32);
        u64 cA[4] = {0,0,0,0};
        u64 cB[4] = {0,0,0,0};
        #pragma unroll
        for (int i = 0; i < 8; i++) {
            ulonglong2 t = kr[i];
            if constexpr (DOA) {
                fma2(cA[(2*i) & 3],   q2A[2*i],   t.x);
                fma2(cA[(2*i+1) & 3], q2A[2*i+1], t.y);
            }
            fma2(cB[(2*i) & 3],   q2B[2*i],   t.x);
            fma2(cB[(2*i+1) & 3], q2B[2*i+1], t.y);
        }
        const float fk = (float)(k0 + kk);
        float wA = 0.f, wB = 0.f;
        if constexpr (DOA) {
            u64 r = add2(add2(cA[0], cA[1]), add2(cA[2], cA[3]));
            float lo, hi; unpk2(r, lo, hi);
            float part = lo + hi;
            float dot  = part + __shfl_xor_sync(0xffffffffu, part, 1);
            float lg = fminf(fmaxf(fmaf(dot, SCALE, LAM * (fk - fqA)), -CLV), CLV);
            float beta = vA ? __fdividef(1.f, 1.f + __expf(-lg)) : 0.f;
            wA = beta * remA;
            remA = fmaxf(remA * (1.f - wA), EPSV);
            wsA += wA;
        }
        {
            u64 r = add2(add2(cB[0], cB[1]), add2(cB[2], cB[3]));
            float lo, hi; unpk2(r, lo, hi);
            float part = lo + hi;
            float dot  = part + __shfl_xor_sync(0xffffffffu, part, 1);
            float lg = fminf(fmaxf(fmaf(dot, SCALE, LAM * (fk - fqB)), -CLV), CLV);
            float beta = vB ? __fdividef(1.f, 1.f + __expf(-lg)) : 0.f;
            wB = beta * remB;
            remB = fmaxf(remB * (1.f - wB), EPSV);
            wsB += wB;
        }
        const ulonglong2* vr = (const ulonglong2*)(shv + kk * HD + half * 32);
        u64 w2A = pk2(wA, wA);
        u64 w2B = pk2(wB, wB);
        #pragma unroll
        for (int i = 0; i < 8; i++) {
            ulonglong2 t = vr[i];
            if constexpr (DOA) {
                fma2(accA[2*i],   w2A, t.x);
                fma2(accA[2*i+1], w2A, t.y);
            }
            fma2(accB[2*i],   w2B, t.x);
            fma2(accB[2*i+1], w2B, t.y);
        }
    };

    // ---- stream k-tiles strictly in ascending order (scan semantics) ----
    for (int kt = 0; kt <= qt; kt++) {
        const int k0 = kt * TK;
        __syncthreads();   // previous tile fully consumed before overwrite
        // Cooperative load: rows via 8 consecutive-row passes (coalesced),
        // RoPE applied to K on the way into shared.
        #pragma unroll 4
        for (int pass = 0; pass < 16; pass++) {
            int row = pass * 8 + (tid >> 4);
            int c4  = tid & 15;
            int pos = k0 + row;
            float4 x = *(const float4*)(gk + base + (size_t)pos * HD + c4 * 4);
            float2 c = *(const float2*)(gcos + pos * 32 + c4 * 2);
            float2 s = *(const float2*)(gsin + pos * 32 + c4 * 2);
            float4 kr;
            kr.x = x.x*c.x - x.y*s.x; kr.y = x.y*c.x + x.x*s.x;
            kr.z = x.z*c.y - x.w*s.y; kr.w = x.w*c.y + x.z*s.y;
            *(float4*)(shk + row * HD + c4 * 4) = kr;
            *(float4*)(shv + row * HD + c4 * 4) =
                *(const float4*)(gv + base + (size_t)pos * HD + c4 * 4);
        }
        __syncthreads();

        if (kt < qt) {
            #pragma unroll 2
            for (int kk = 0; kk < TK; kk++) step(kk, k0, TrueT{}, true, true);
        } else {
            // diagonal tile: kk in [0,64) touches both queries (A predicated),
            // kk in [64,128) touches only query B (A's FMAs elided at compile time)
            #pragma unroll 2
            for (int kk = 0; kk < 64; kk++) step(kk, k0, TrueT{}, kk <= p, true);
            #pragma unroll 2
            for (int kk = 64; kk < TK; kk++) step(kk, k0, FalseT{}, false, (kk - 64) <= p);
        }
    }

    // ---- normalize and write out ----
    float invA = __fdividef(1.f, fmaxf(wsA, EPSV));
    float invB = __fdividef(1.f, fmaxf(wsB, EPSV));
    u64 i2A = pk2(invA, invA);
    u64 i2B = pk2(invB, invB);
    float* oa = gout + base + (size_t)qA * HD + half * 32;
    float* ob = gout + base + (size_t)qB * HD + half * 32;
    #pragma unroll
    for (int i = 0; i < 8; i++) {
        ulonglong2 tA;
        tA.x = mul2(accA[2*i], i2A);
        tA.y = mul2(accA[2*i+1], i2A);
        *(ulonglong2*)(oa + 4 * i) = tA;
        ulonglong2 tB;
        tB.x = mul2(accB[2*i], i2B);
        tB.y = mul2(accB[2*i+1], i2B);
        *(ulonglong2*)(ob + 4 * i) = tB;
    }
}

extern "C" void kernel_launch(void* const* d_in, const int* in_sizes, int n_in,
                              void* d_out, int out_size)
{
    (void)in_sizes; (void)n_in; (void)out_size;
    const float* q    = (const float*)d_in[0];
    const float* k    = (const float*)d_in[1];
    const float* v    = (const float*)d_in[2];
    const float* cosc = (const float*)d_in[3];
    const float* sinc = (const float*)d_in[4];
    float* out = (float*)d_out;

    const int smem_bytes = 2 * TK * HD * (int)sizeof(float);  // 64 KiB
    cudaFuncSetAttribute(rse_attn, cudaFuncAttributeMaxDynamicSharedMemorySize,
                         smem_bytes);
    rse_attn<<<NQT * BHN, NTHREADS, smem_bytes>>>(q, k, v, cosc, sinc, out);
}

// round 2
// speedup vs baseline: 1.1799x; 1.1799x over previous
#include <cuda_runtime.h>
#include <cstdint>

#define NB    4
#define NH    12
#define BHN   48
#define SEQ   1024
#define HD    64
#define TQ    128         // queries per CTA
#define TK    64          // keys per half-tile
#define NQT   (SEQ / TQ)  // 8
#define NTHREADS 128
#define LAM   0.01f
#define EPSV  1e-6f
#define CLV   20.0f
#define SCALE 0.125f

#define WSTRIDE 132       // padded W row (floats), 16B-aligned

typedef unsigned long long u64;

__device__ __forceinline__ u64 pk2(float lo, float hi) {
    u64 r; asm("mov.b64 %0, {%1,%2};" : "=l"(r) : "f"(lo), "f"(hi)); return r;
}
__device__ __forceinline__ void unpk2(u64 v, float& lo, float& hi) {
    asm("mov.b64 {%0,%1}, %2;" : "=f"(lo), "=f"(hi) : "l"(v));
}
__device__ __forceinline__ void fma2(u64& d, u64 a, u64 b) {
    asm("fma.rn.f32x2 %0, %1, %2, %0;" : "+l"(d) : "l"(a), "l"(b));
}
__device__ __forceinline__ u64 add2(u64 a, u64 b) {
    u64 r; asm("add.rn.f32x2 %0, %1, %2;" : "=l"(r) : "l"(a), "l"(b)); return r;
}
__device__ __forceinline__ u64 mul2(u64 a, u64 b) {
    u64 r; asm("mul.rn.f32x2 %0, %1, %2;" : "=l"(r) : "l"(a), "l"(b)); return r;
}

// smem: shk[64][64] | shv[64][64] | shw[64][WSTRIDE]
#define SHK_OFF 0
#define SHV_OFF (TK * HD)
#define SHW_OFF (2 * TK * HD)
#define SMEM_FLOATS (2 * TK * HD + TK * WSTRIDE)

__global__ void __launch_bounds__(NTHREADS, 2)
rse_attn(const float* __restrict__ gq, const float* __restrict__ gk,
         const float* __restrict__ gv, const float* __restrict__ gcos,
         const float* __restrict__ gsin, float* __restrict__ gout)
{
    extern __shared__ float smem[];
    float* shk = smem + SHK_OFF;
    float* shv = smem + SHV_OFF;
    float* shw = smem + SHW_OFF;

    const int tid  = threadIdx.x;
    const int idx  = blockIdx.x;
    const int qt   = (NQT - 1) - (idx / BHN);   // heavy q-tiles first
    const int bh   = idx % BHN;
    const int q0   = qt * TQ;
    const int half = tid & 1;
    const int p    = tid >> 1;                  // 0..63
    const int qA   = q0 + p;
    const int qB   = q0 + 64 + p;
    // scan identity of this lane: even -> qA, odd -> qB
    const int   qi  = half ? (p + 64) : p;      // local query index for W/wsum
    const float fqS = (float)(half ? qB : qA);
    const size_t base = (size_t)bh * SEQ * HD;

    // V-GEMM identity: 8 queries x 8 dims per thread
    const int qg = tid & 15;    // query group: q = qg*8 .. +8
    const int dg = tid >> 4;    // dim group:   d = dg*8 .. +8

    // ---- load + RoPE two query rows (32 dims per lane = 16 f32x2) ----
    u64 q2A[16], q2B[16];
    {
        const float* ra = gq + base + (size_t)qA * HD + half * 32;
        const float* rb = gq + base + (size_t)qB * HD + half * 32;
        const float* ca = gcos + qA * 32 + half * 16;
        const float* sa = gsin + qA * 32 + half * 16;
        const float* cb = gcos + qB * 32 + half * 16;
        const float* sb = gsin + qB * 32 + half * 16;
        #pragma unroll
        for (int j = 0; j < 8; j++) {
            float4 x  = *(const float4*)(ra + 4 * j);
            float2 c  = *(const float2*)(ca + 2 * j);
            float2 s  = *(const float2*)(sa + 2 * j);
            q2A[2*j]   = pk2(x.x*c.x - x.y*s.x, x.y*c.x + x.x*s.x);
            q2A[2*j+1] = pk2(x.z*c.y - x.w*s.y, x.w*c.y + x.z*s.y);
            float4 y  = *(const float4*)(rb + 4 * j);
            float2 c2 = *(const float2*)(cb + 2 * j);
            float2 s2 = *(const float2*)(sb + 2 * j);
            q2B[2*j]   = pk2(y.x*c2.x - y.y*s2.x, y.y*c2.x + y.x*s2.x);
            q2B[2*j+1] = pk2(y.z*c2.y - y.w*s2.y, y.w*c2.y + y.z*s2.y);
        }
    }

    u64 acc[8][4];
    #pragma unroll
    for (int j = 0; j < 8; j++)
        #pragma unroll
        for (int i = 0; i < 4; i++) acc[j][i] = 0ull;
    float rem = 1.f, ws = 0.f;

    const int nhalf = 2 * qt + 2;
    for (int h = 0; h < nhalf; h++) {
        const int k0 = h * TK;
        __syncthreads();   // prev V-GEMM done before overwriting shk/shv

        // ---- load K (RoPE'd) and V tile: 64 rows ----
        #pragma unroll
        for (int pass = 0; pass < 8; pass++) {
            int row = pass * 8 + (tid >> 4);
            int c4  = tid & 15;
            int pos = k0 + row;
            float4 x = *(const float4*)(gk + base + (size_t)pos * HD + c4 * 4);
            float2 c = *(const float2*)(gcos + pos * 32 + c4 * 2);
            float2 s = *(const float2*)(gsin + pos * 32 + c4 * 2);
            float4 kr;
            kr.x = x.x*c.x - x.y*s.x; kr.y = x.y*c.x + x.x*s.x;
            kr.z = x.z*c.y - x.w*s.y; kr.w = x.w*c.y + x.z*s.y;
            *(float4*)(shk + row * HD + c4 * 4) = kr;
            *(float4*)(shv + row * HD + c4 * 4) =
                *(const float4*)(gv + base + (size_t)pos * HD + c4 * 4);
        }
        __syncthreads();

        // ---- phase 1: dots (chunks of 8 keys) + scan, write w to shw ----
        #pragma unroll 2
        for (int c = 0; c < 8; c++) {
            u64 dA[8], dB[8];
            #pragma unroll
            for (int kk = 0; kk < 8; kk++) {
                const ulonglong2* kr =
                    (const ulonglong2*)(shk + (c * 8 + kk) * HD + half * 32);
                u64 a0 = 0, a1 = 0, b0 = 0, b1 = 0;
                #pragma unroll
                for (int i = 0; i < 4; i++) {
                    ulonglong2 t  = kr[2*i];
                    ulonglong2 t2 = kr[2*i+1];
                    fma2(a0, q2A[4*i],   t.x);  fma2(a1, q2A[4*i+1], t.y);
                    fma2(b0, q2B[4*i],   t.x);  fma2(b1, q2B[4*i+1], t.y);
                    fma2(a0, q2A[4*i+2], t2.x); fma2(a1, q2A[4*i+3], t2.y);
                    fma2(b0, q2B[4*i+2], t2.x); fma2(b1, q2B[4*i+3], t2.y);
                }
                dA[kk] = add2(a0, a1);
                dB[kk] = add2(b0, b1);
            }
            float fk = (float)(k0 + c * 8);
            #pragma unroll
            for (int kk = 0; kk < 8; kk++) {
                float aLo, aHi, bLo, bHi;
                unpk2(dA[kk], aLo, aHi);
                unpk2(dB[kk], bLo, bHi);
                float pA = aLo + aHi, pB = bLo + bHi;
                float give = half ? pA : pB;
                float got  = __shfl_xor_sync(0xffffffffu, give, 1);
                float mine = half ? pB : pA;
                float dot  = mine + got;
                float lg = fmaf(dot, SCALE, (fk - fqS) * LAM);
                lg = fminf(fmaxf(lg, -CLV), CLV);
                lg = (fk <= fqS) ? lg : -CLV;
                float beta = __fdividef(1.f, 1.f + __expf(-lg));
                float w = beta * rem;
                rem = fmaxf(fmaf(-w, rem, rem), EPSV);
                ws += w;
                shw[(c * 8 + kk) * WSTRIDE + qi] = w;
                fk += 1.f;
            }
        }
        __syncthreads();

        // ---- phase 2: O[q][d] += W[k][q] * V[k][d], 8q x 8d per thread ----
        #pragma unroll 4
        for (int k = 0; k < TK; k++) {
            const float* wr = shw + k * WSTRIDE + qg * 8;
            float4 w0 = *(const float4*)(wr);
            float4 w1 = *(const float4*)(wr + 4);
            const ulonglong2* vr = (const ulonglong2*)(shv + k * HD + dg * 8);
            ulonglong2 va = vr[0];
            ulonglong2 vb = vr[1];
            u64 s;
            s = pk2(w0.x, w0.x);
            fma2(acc[0][0], s, va.x); fma2(acc[0][1], s, va.y);
            fma2(acc[0][2], s, vb.x); fma2(acc[0][3], s, vb.y);
            s = pk2(w0.y, w0.y);
            fma2(acc[1][0], s, va.x); fma2(acc[1][1], s, va.y);
            fma2(acc[1][2], s, vb.x); fma2(acc[1][3], s, vb.y);
            s = pk2(w0.z, w0.z);
            fma2(acc[2][0], s, va.x); fma2(acc[2][1], s, va.y);
            fma2(acc[2][2], s, vb.x); fma2(acc[2][3], s, vb.y);
            s = pk2(w0.w, w0.w);
            fma2(acc[3][0], s, va.x); fma2(acc[3][1], s, va.y);
            fma2(acc[3][2], s, vb.x); fma2(acc[3][3], s, vb.y);
            s = pk2(w1.x, w1.x);
            fma2(acc[4][0], s, va.x); fma2(acc[4][1], s, va.y);
            fma2(acc[4][2], s, vb.x); fma2(acc[4][3], s, vb.y);
            s = pk2(w1.y, w1.y);
            fma2(acc[5][0], s, va.x); fma2(acc[5][1], s, va.y);
            fma2(acc[5][2], s, vb.x); fma2(acc[5][3], s, vb.y);
            s = pk2(w1.z, w1.z);
            fma2(acc[6][0], s, va.x); fma2(acc[6][1], s, va.y);
            fma2(acc[6][2], s, vb.x); fma2(acc[6][3], s, vb.y);
            s = pk2(w1.w, w1.w);
            fma2(acc[7][0], s, va.x); fma2(acc[7][1], s, va.y);
            fma2(acc[7][2], s, vb.x); fma2(acc[7][3], s, vb.y);
        }
    }

    // ---- epilogue: share wsum, normalize, write out ----
    __syncthreads();
    shw[qi] = ws;
    __syncthreads();
    float4 s0 = *(const float4*)(shw + qg * 8);
    float4 s1 = *(const float4*)(shw + qg * 8 + 4);
    float inv[8];
    inv[0] = __fdividef(1.f, fmaxf(s0.x, EPSV));
    inv[1] = __fdividef(1.f, fmaxf(s0.y, EPSV));
    inv[2] = __fdividef(1.f, fmaxf(s0.z, EPSV));
    inv[3] = __fdividef(1.f, fmaxf(s0.w, EPSV));
    inv[4] = __fdividef(1.f, fmaxf(s1.x, EPSV));
    inv[5] = __fdividef(1.f, fmaxf(s1.y, EPSV));
    inv[6] = __fdividef(1.f, fmaxf(s1.z, EPSV));
    inv[7] = __fdividef(1.f, fmaxf(s1.w, EPSV));
    float* orow = gout + base + (size_t)(q0 + qg * 8) * HD + dg * 8;
    #pragma unroll
    for (int j = 0; j < 8; j++) {
        u64 i2 = pk2(inv[j], inv[j]);
        ulonglong2 o;
        o.x = mul2(acc[j][0], i2);
        o.y = mul2(acc[j][1], i2);
        *(ulonglong2*)(orow + (size_t)j * HD) = o;
        o.x = mul2(acc[j][2], i2);
        o.y = mul2(acc[j][3], i2);
        *(ulonglong2*)(orow + (size_t)j * HD + 4) = o;
    }
}

extern "C" void kernel_launch(void* const* d_in, const int* in_sizes, int n_in,
                              void* d_out, int out_size)
{
    (void)in_sizes; (void)n_in; (void)out_size;
    const float* q    = (const float*)d_in[0];
    const float* k    = (const float*)d_in[1];
    const float* v    = (const float*)d_in[2];
    const float* cosc = (const float*)d_in[3];
    const float* sinc = (const float*)d_in[4];
    float* out = (float*)d_out;

    const int smem_bytes = SMEM_FLOATS * (int)sizeof(float);  // ~65 KB
    cudaFuncSetAttribute(rse_attn, cudaFuncAttributeMaxDynamicSharedMemorySize,
                         smem_bytes);
    rse_attn<<<NQT * BHN, NTHREADS, smem_bytes>>>(q, k, v, cosc, sinc, out);
}